// round 12
// baseline (speedup 1.0000x reference)
#include <cuda_runtime.h>
#include <math.h>
#include <stdint.h>

#define L_  12
#define H_  12
#define D_  768
#define DH_ 64
#define FF_ 3072
#define B_  32
#define S_  256
#define NT_ (B_*S_)     /* 8192 tokens */
#define QKV_ (3*D_)     /* 2304 */

/* ---------------- scratch (device globals; no allocations) ---------------- */
__device__ float g_x[NT_*D_];
__device__ float g_qkv[(size_t)NT_*QKV_];
__device__ float g_a[NT_*D_];
__device__ float g_t[NT_*D_];
__device__ float g_h[(size_t)NT_*FF_];
__device__ float g_sk[64*64];
__device__ float g_pq[32*64];
/* transposed weights: [l][N][K] so GEMM B-operand is n-major */
__device__ float g_wqkvT[(size_t)L_*QKV_*D_];
__device__ float g_bqkv[L_*QKV_];
__device__ float g_woT[L_*D_*D_];
__device__ float g_w1T[(size_t)L_*D_*FF_];
__device__ float g_w2T[(size_t)L_*D_*FF_];

/* ------ tiled transpose: src[z][K][N] -> dst[z (dst_ls)][row_off + N][K] -- */
__global__ void transpose_f32(const float* __restrict__ src, float* __restrict__ dst,
                              int K, int N, size_t src_ls, size_t dst_ls, int row_off)
{
    __shared__ float tile[32][33];
    size_t soff = (size_t)blockIdx.z * src_ls;
    size_t doff = (size_t)blockIdx.z * dst_ls;
    int n0 = blockIdx.x * 32, k0 = blockIdx.y * 32;
    int tx = threadIdx.x, ty = threadIdx.y;
    #pragma unroll
    for (int i = 0; i < 32; i += 8)
        tile[ty + i][tx] = src[soff + (size_t)(k0 + ty + i) * N + n0 + tx];
    __syncthreads();
    #pragma unroll
    for (int i = 0; i < 32; i += 8)
        dst[doff + (size_t)(row_off + n0 + ty + i) * K + k0 + tx] = tile[tx][ty + i];
}

/* ---------------- concat QKV biases: [L][3*D] ---------------- */
__global__ void concat_bias_kernel(const float* __restrict__ bq, const float* __restrict__ bk,
                                   const float* __restrict__ bv, float* __restrict__ bqkv)
{
    int i = blockIdx.x*256 + threadIdx.x;
    if (i >= L_*QKV_) return;
    int l = i / QKV_, c = i % QKV_;
    float val = (c < D_) ? bq[l*D_ + c]
              : (c < 2*D_) ? bk[l*D_ + c - D_]
              : bv[l*D_ + c - 2*D_];
    bqkv[i] = val;
}

/* ---------------- block reduction (256 threads) ---------------- */
__device__ __forceinline__ float block_sum_256(float v, float* red) {
    int lane = threadIdx.x & 31, w = threadIdx.x >> 5;
    #pragma unroll
    for (int o = 16; o > 0; o >>= 1) v += __shfl_down_sync(0xffffffffu, v, o);
    if (lane == 0) red[w] = v;
    __syncthreads();
    if (w == 0) {
        float x = (lane < 8) ? red[lane] : 0.f;
        #pragma unroll
        for (int o = 4; o > 0; o >>= 1) x += __shfl_down_sync(0xffffffffu, x, o);
        if (lane == 0) red[32] = x;
    }
    __syncthreads();
    return red[32];
}

/* ---------------- embeddings + LayerNorm ---------------- */
__global__ void embed_ln_kernel(const int* __restrict__ ids, const int* __restrict__ tt,
                                const float* __restrict__ we, const float* __restrict__ pe,
                                const float* __restrict__ te, const float* __restrict__ g,
                                const float* __restrict__ b, float* __restrict__ x)
{
    int row = blockIdx.x;
    int s = row & (S_-1);
    int id = ids[row], t = tt[row];
    __shared__ float buf[D_];
    __shared__ float red[40];
    int tid = threadIdx.x;
    float ps = 0.f;
    #pragma unroll
    for (int i = 0; i < 3; i++) {
        int d = tid + i*256;
        float e = we[(size_t)id*D_ + d] + pe[s*D_ + d] + te[t*D_ + d];
        buf[d] = e; ps += e;
    }
    __syncthreads();
    float mean = block_sum_256(ps, red) * (1.f/D_);
    float pv = 0.f;
    #pragma unroll
    for (int i = 0; i < 3; i++) { int d = tid + i*256; float c = buf[d]-mean; pv += c*c; }
    float var = block_sum_256(pv, red) * (1.f/D_);
    float inv = rsqrtf(var + 1e-12f);
    #pragma unroll
    for (int i = 0; i < 3; i++) {
        int d = tid + i*256;
        x[(size_t)row*D_ + d] = (buf[d]-mean)*inv*g[d] + b[d];
    }
}

/* ----------- pure LayerNorm: x = LN(t) (residual pre-added in GEMM) ------- */
__global__ void ln_kernel(const float* __restrict__ t, float* __restrict__ x,
                          const float* __restrict__ g, const float* __restrict__ b)
{
    int row = blockIdx.x;
    __shared__ float buf[D_];
    __shared__ float red[40];
    int tid = threadIdx.x;
    float ps = 0.f;
    #pragma unroll
    for (int i = 0; i < 3; i++) {
        int d = tid + i*256;
        float e = t[(size_t)row*D_ + d];
        buf[d] = e; ps += e;
    }
    __syncthreads();
    float mean = block_sum_256(ps, red) * (1.f/D_);
    float pv = 0.f;
    #pragma unroll
    for (int i = 0; i < 3; i++) { int d = tid + i*256; float c = buf[d]-mean; pv += c*c; }
    float var = block_sum_256(pv, red) * (1.f/D_);
    float inv = rsqrtf(var + 1e-12f);
    #pragma unroll
    for (int i = 0; i < 3; i++) {
        int d = tid + i*256;
        x[(size_t)row*D_ + d] = (buf[d]-mean)*inv*g[d] + b[d];
    }
}

/* ---------------- tf32 mma primitives ---------------- */
__device__ __forceinline__ void cpasync16(void* smem, const void* gmem) {
    uint32_t s = (uint32_t)__cvta_generic_to_shared(smem);
    asm volatile("cp.async.ca.shared.global [%0], [%1], 16;\n" :: "r"(s), "l"(gmem));
}
__device__ __forceinline__ void cp_commit() { asm volatile("cp.async.commit_group;\n"); }
__device__ __forceinline__ void cp_wait0()  { asm volatile("cp.async.wait_group 0;\n"); }

__device__ __forceinline__ void ldsm_x4(uint32_t* r, uint32_t saddr) {
    asm volatile("ldmatrix.sync.aligned.m8n8.x4.shared.b16 {%0,%1,%2,%3}, [%4];"
                 : "=r"(r[0]), "=r"(r[1]), "=r"(r[2]), "=r"(r[3]) : "r"(saddr));
}
__device__ __forceinline__ void mma_tf32(float* d, const uint32_t* a, const uint32_t* b) {
    asm volatile(
        "mma.sync.aligned.m16n8k8.row.col.f32.tf32.tf32.f32 "
        "{%0,%1,%2,%3}, {%4,%5,%6,%7}, {%8,%9}, {%0,%1,%2,%3};\n"
        : "+f"(d[0]), "+f"(d[1]), "+f"(d[2]), "+f"(d[3])
        : "r"(a[0]), "r"(a[1]), "r"(a[2]), "r"(a[3]), "r"(b[0]), "r"(b[1]));
}

/* ====== tf32 tensor-core GEMM, BK=32, ldmatrix, optional residual ======
 * C = A @ BT^T + bias [+ resid] [gelu]. Dynamic smem (73.7KB). */
#define GPAD 36   /* row stride: offsets {0,4,8,...,28} mod 32 — conflict-free */
#define GA_ST (128*GPAD)
#define GSM_FLOATS (4*GA_ST)            /* 2 stages A + 2 stages B */
#define GSM_BYTES  (GSM_FLOATS*4)       /* 73728 */

__global__ __launch_bounds__(256, 2)
void gemm_tf32_ldsm(const float* __restrict__ A, const float* __restrict__ BT,
                    const float* __restrict__ bias, const float* __restrict__ resid,
                    float* __restrict__ C, int M, int N, int K, int gelu)
{
    extern __shared__ __align__(16) float sm[];
    /* AS(st,m,k) / BS(st,n,k) */
    #define AS_(st,m,k) sm[(st)*GA_ST + (m)*GPAD + (k)]
    #define BS_(st,n,k) sm[2*GA_ST + (st)*GA_ST + (n)*GPAD + (k)]

    const int tid  = threadIdx.x;
    const int brow = blockIdx.y * 128;
    const int bcol = blockIdx.x * 128;
    const int lane = tid & 31;
    const int wid  = tid >> 5;
    const int g    = lane >> 2;
    const int tg   = lane & 3;
    const int wm   = (wid & 1) * 64;
    const int wn   = (wid >> 1) * 32;

    const int a_m = lane & 15;
    const int a_k = (lane >> 4) << 2;
    const int b_n = (lane & 7) + ((lane >> 4) << 3);
    const int b_k = ((lane >> 3) & 1) << 2;

    float acc[4][4][4];
    #pragma unroll
    for (int mt = 0; mt < 4; mt++)
        #pragma unroll
        for (int nt = 0; nt < 4; nt++)
            #pragma unroll
            for (int i = 0; i < 4; i++) acc[mt][nt][i] = 0.f;

    /* loader: tile 128x32 = 1024 chunks of 16B; 4 chunks/thread */
    const int lr0 = tid >> 1;                 /* rows 0..127 (2 threads/row) */
    const int lc0 = (tid & 1) << 4;           /* col 0 or 16 */

    #define LOAD_STAGE(buf, k0) do {                                                     \
        cpasync16(&AS_(buf, lr0, lc0    ), A  + (size_t)(brow + lr0)*K + (k0) + lc0    ); \
        cpasync16(&AS_(buf, lr0, lc0 + 4), A  + (size_t)(brow + lr0)*K + (k0) + lc0 + 4); \
        cpasync16(&AS_(buf, lr0, lc0 + 8), A  + (size_t)(brow + lr0)*K + (k0) + lc0 + 8); \
        cpasync16(&AS_(buf, lr0, lc0 +12), A  + (size_t)(brow + lr0)*K + (k0) + lc0 +12); \
        cpasync16(&BS_(buf, lr0, lc0    ), BT + (size_t)(bcol + lr0)*K + (k0) + lc0    ); \
        cpasync16(&BS_(buf, lr0, lc0 + 4), BT + (size_t)(bcol + lr0)*K + (k0) + lc0 + 4); \
        cpasync16(&BS_(buf, lr0, lc0 + 8), BT + (size_t)(bcol + lr0)*K + (k0) + lc0 + 8); \
        cpasync16(&BS_(buf, lr0, lc0 +12), BT + (size_t)(bcol + lr0)*K + (k0) + lc0 +12); \
        cp_commit();                                                                     \
    } while (0)

    LOAD_STAGE(0, 0);

    const int nk = K >> 5;
    for (int it = 0; it < nk; it++) {
        cp_wait0();
        __syncthreads();
        const int cur = it & 1;
        if (it + 1 < nk) LOAD_STAGE(cur ^ 1, (it + 1) << 5);

        #pragma unroll
        for (int kk = 0; kk < 32; kk += 8) {
            uint32_t afr[4][4];
            #pragma unroll
            for (int mt = 0; mt < 4; mt++) {
                uint32_t addr = (uint32_t)__cvta_generic_to_shared(
                    &AS_(cur, wm + mt*16 + a_m, kk + a_k));
                ldsm_x4(afr[mt], addr);
            }
            uint32_t bfr[2][4];
            #pragma unroll
            for (int np = 0; np < 2; np++) {
                uint32_t addr = (uint32_t)__cvta_generic_to_shared(
                    &BS_(cur, wn + np*16 + b_n, kk + b_k));
                ldsm_x4(bfr[np], addr);
            }
            #pragma unroll
            for (int mt = 0; mt < 4; mt++)
                #pragma unroll
                for (int nt = 0; nt < 4; nt++)
                    mma_tf32(acc[mt][nt], afr[mt], &bfr[nt >> 1][(nt & 1) * 2]);
        }
    }

    #pragma unroll
    for (int mt = 0; mt < 4; mt++) {
        #pragma unroll
        for (int nt = 0; nt < 4; nt++) {
            int row0 = brow + wm + mt*16 + g;
            int col  = bcol + wn + nt*8 + tg*2;
            float b0 = bias[col], b1 = bias[col + 1];
            float c0 = acc[mt][nt][0] + b0;
            float c1 = acc[mt][nt][1] + b1;
            float c2 = acc[mt][nt][2] + b0;
            float c3 = acc[mt][nt][3] + b1;
            if (resid) {
                float2 r0 = *(const float2*)(resid + (size_t)row0*N + col);
                float2 r1 = *(const float2*)(resid + (size_t)(row0 + 8)*N + col);
                c0 += r0.x; c1 += r0.y; c2 += r1.x; c3 += r1.y;
            }
            if (gelu) {
                c0 = 0.5f*c0*(1.f + erff(c0*0.70710678118654752f));
                c1 = 0.5f*c1*(1.f + erff(c1*0.70710678118654752f));
                c2 = 0.5f*c2*(1.f + erff(c2*0.70710678118654752f));
                c3 = 0.5f*c3*(1.f + erff(c3*0.70710678118654752f));
            }
            *(float2*)(C + (size_t)row0*N + col)       = make_float2(c0, c1);
            *(float2*)(C + (size_t)(row0 + 8)*N + col) = make_float2(c2, c3);
        }
    }
}

/* ============ tensor-core flash attention v2 (tf32, low-reg) ============ */
__global__ __launch_bounds__(128)
void attention_tc2(const float* __restrict__ qkv, const int* __restrict__ mask,
                   float* __restrict__ o)
{
    __shared__ __align__(16) float Ks[2][32][68];
    __shared__ __align__(16) float Vt[2][64][36];
    __shared__ __align__(16) float Ps[4][16][36];
    __shared__ float mb[S_];

    const int qq = blockIdx.x, h = blockIdx.y, b = blockIdx.z;
    const int tid = threadIdx.x, lane = tid & 31, w = tid >> 5;
    const int g = lane >> 2, tg = lane & 3;
    const int a_m = lane & 15;
    const int a_k = (lane >> 4) << 2;
    const int b_n = (lane & 7) + ((lane >> 4) << 3);
    const int b_k = ((lane >> 3) & 1) << 2;

    const size_t baseq = (size_t)b * S_ * QKV_ + (size_t)h * DH_;
    const size_t basek = baseq + D_;
    const size_t basev = baseq + 2*D_;
    const size_t baseo = (size_t)b * S_ * D_ + (size_t)h * DH_;
    const int q0 = qq*64 + w*16;

    mb[tid]       = mask[b*S_ + tid]       ? 0.f : -10000.f;
    mb[tid + 128] = mask[b*S_ + tid + 128] ? 0.f : -10000.f;

    float qf[8][4];
    #pragma unroll
    for (int kt = 0; kt < 8; kt++) {
        const float* qp = qkv + baseq + (size_t)(q0 + g)*QKV_ + kt*8 + tg;
        qf[kt][0] = 0.125f * qp[0];
        qf[kt][1] = 0.125f * qp[(size_t)8*QKV_];
        qf[kt][2] = 0.125f * qp[4];
        qf[kt][3] = 0.125f * qp[(size_t)8*QKV_ + 4];
    }

    float O[8][4];
    #pragma unroll
    for (int nt = 0; nt < 8; nt++)
        #pragma unroll
        for (int i = 0; i < 4; i++) O[nt][i] = 0.f;
    float mrow[2] = {-1e30f, -1e30f};
    float lrow[2] = {0.f, 0.f};

    const int kr = tid >> 2, kc = (tid & 3) << 2;
    const int vr = tid >> 2, vcb = (tid & 3) << 4;

    auto att_load_k = [&](int buf, int kv0) {
        cpasync16(&Ks[buf][kr][kc     ], qkv + basek + (size_t)(kv0 + kr)*QKV_ + kc     );
        cpasync16(&Ks[buf][kr][kc + 16], qkv + basek + (size_t)(kv0 + kr)*QKV_ + kc + 16);
        cpasync16(&Ks[buf][kr][kc + 32], qkv + basek + (size_t)(kv0 + kr)*QKV_ + kc + 32);
        cpasync16(&Ks[buf][kr][kc + 48], qkv + basek + (size_t)(kv0 + kr)*QKV_ + kc + 48);
        cp_commit();
    };

    float vreg[16];
    auto att_ldg_v = [&](int kv0) {
        #pragma unroll
        for (int j = 0; j < 4; j++)
            *(float4*)&vreg[4*j] =
                *(const float4*)(qkv + basev + (size_t)(kv0 + vr)*QKV_ + vcb + 4*j);
    };

    auto att_sts_v = [&](int buf) {
        #pragma unroll
        for (int s = 0; s < 16; s++) {
            int jj = (s + ((tid & 3) << 2)) & 15;
            Vt[buf][vcb + jj][vr] = vreg[jj];
        }
    };

    att_load_k(0, 0);
    att_ldg_v(0);
    att_sts_v(0);

    for (int it = 0; it < S_/32; it++) {
        cp_wait0();
        __syncthreads();
        const int cur = it & 1;
        const int kv0 = it*32;
        if (it + 1 < S_/32) {
            att_load_k(cur ^ 1, kv0 + 32);
            att_ldg_v(kv0 + 32);
        }

        float sc[4][4];
        #pragma unroll
        for (int nt = 0; nt < 4; nt++)
            #pragma unroll
            for (int i = 0; i < 4; i++) sc[nt][i] = 0.f;
        #pragma unroll
        for (int kt = 0; kt < 8; kt++) {
            uint32_t bfr[2][4];
            #pragma unroll
            for (int np = 0; np < 2; np++) {
                uint32_t addr = (uint32_t)__cvta_generic_to_shared(
                    &Ks[cur][np*16 + b_n][kt*8 + b_k]);
                ldsm_x4(bfr[np], addr);
            }
            #pragma unroll
            for (int nt = 0; nt < 4; nt++)
                mma_tf32(sc[nt], (const uint32_t*)qf[kt],
                         &bfr[nt >> 1][(nt & 1) * 2]);
        }

        #pragma unroll
        for (int nt = 0; nt < 4; nt++) {
            float m0 = mb[kv0 + nt*8 + 2*tg], m1 = mb[kv0 + nt*8 + 2*tg + 1];
            sc[nt][0] += m0; sc[nt][1] += m1;
            sc[nt][2] += m0; sc[nt][3] += m1;
        }
        #pragma unroll
        for (int rh = 0; rh < 2; rh++) {
            float mx = -1e30f;
            #pragma unroll
            for (int nt = 0; nt < 4; nt++)
                mx = fmaxf(mx, fmaxf(sc[nt][2*rh], sc[nt][2*rh+1]));
            mx = fmaxf(mx, __shfl_xor_sync(0xffffffffu, mx, 1));
            mx = fmaxf(mx, __shfl_xor_sync(0xffffffffu, mx, 2));
            float nm = fmaxf(mrow[rh], mx);
            float scale = __expf(mrow[rh] - nm);
            mrow[rh] = nm;
            float rs = 0.f;
            #pragma unroll
            for (int nt = 0; nt < 4; nt++) {
                float e0 = __expf(sc[nt][2*rh]   - nm);
                float e1 = __expf(sc[nt][2*rh+1] - nm);
                sc[nt][2*rh] = e0; sc[nt][2*rh+1] = e1;
                rs += e0 + e1;
            }
            rs += __shfl_xor_sync(0xffffffffu, rs, 1);
            rs += __shfl_xor_sync(0xffffffffu, rs, 2);
            lrow[rh] = lrow[rh]*scale + rs;
            #pragma unroll
            for (int nt = 0; nt < 8; nt++) {
                O[nt][2*rh]   *= scale;
                O[nt][2*rh+1] *= scale;
            }
        }
        #pragma unroll
        for (int nt = 0; nt < 4; nt++) {
            *(float2*)&Ps[w][g    ][nt*8 + 2*tg] = make_float2(sc[nt][0], sc[nt][1]);
            *(float2*)&Ps[w][g + 8][nt*8 + 2*tg] = make_float2(sc[nt][2], sc[nt][3]);
        }
        __syncwarp();

        #pragma unroll
        for (int kt = 0; kt < 4; kt++) {
            uint32_t pf[4];
            {
                uint32_t addr = (uint32_t)__cvta_generic_to_shared(
                    &Ps[w][a_m][kt*8 + a_k]);
                ldsm_x4(pf, addr);
            }
            uint32_t bfr[4][4];
            #pragma unroll
            for (int np = 0; np < 4; np++) {
                uint32_t addr = (uint32_t)__cvta_generic_to_shared(
                    &Vt[cur][np*16 + b_n][kt*8 + b_k]);
                ldsm_x4(bfr[np], addr);
            }
            #pragma unroll
            for (int nt = 0; nt < 8; nt++)
                mma_tf32(O[nt], pf, &bfr[nt >> 1][(nt & 1) * 2]);
        }

        if (it + 1 < S_/32) att_sts_v(cur ^ 1);
    }

    float inv0 = 1.f / lrow[0];
    float inv1 = 1.f / lrow[1];
    #pragma unroll
    for (int nt = 0; nt < 8; nt++) {
        int col = nt*8 + 2*tg;
        *(float2*)(o + baseo + (size_t)(q0 + g)*D_ + col) =
            make_float2(O[nt][0]*inv0, O[nt][1]*inv0);
        *(float2*)(o + baseo + (size_t)(q0 + g + 8)*D_ + col) =
            make_float2(O[nt][2]*inv1, O[nt][3]*inv1);
    }
}

/* ---------------- sense head ---------------- */
__global__ void sense_proj_kernel(const float* __restrict__ sense_emb,
                                  const float* __restrict__ att_Wk, float* __restrict__ sk)
{
    int idx = blockIdx.x*256 + threadIdx.x;
    int j = idx >> 6, a = idx & 63;
    float s = 0.f;
    for (int d = 0; d < D_; d++)
        s += sense_emb[(size_t)j*D_ + d] * att_Wk[(size_t)d*64 + a];
    sk[idx] = s;
}

__global__ void pun_proj_kernel(const float* __restrict__ x, const int* __restrict__ loc,
                                const float* __restrict__ att_Wq, float* __restrict__ pq)
{
    int idx = blockIdx.x*256 + threadIdx.x;
    int b = idx >> 6, a = idx & 63;
    int row = b*S_ + loc[b];
    float s = 0.f;
    for (int d = 0; d < D_; d++)
        s += x[(size_t)row*D_ + d] * att_Wq[(size_t)d*64 + a];
    pq[idx] = s;
}

__global__ void top2_kernel(const float* __restrict__ pq, const float* __restrict__ sk,
                            float* __restrict__ out)
{
    int b = blockIdx.x, j = threadIdx.x;
    __shared__ float sc[64];
    float s = 0.f;
    #pragma unroll 8
    for (int a = 0; a < 64; a++) s += pq[b*64 + a] * sk[j*64 + a];
    sc[j] = s * 0.125f;
    __syncthreads();
    if (j == 0) {
        int i1 = 0; float v1 = sc[0];
        for (int i = 1; i < 64; i++) if (sc[i] > v1) { v1 = sc[i]; i1 = i; }
        int i2 = -1; float v2 = -1e30f;
        for (int i = 0; i < 64; i++) if (i != i1 && sc[i] > v2) { v2 = sc[i]; i2 = i; }
        out[b*2 + 0] = (float)i1;
        out[b*2 + 1] = (float)i2;
    }
}

/* ---------------- launch ---------------- */
extern "C" void kernel_launch(void* const* d_in, const int* in_sizes, int n_in,
                              void* d_out, int out_size)
{
    (void)in_sizes; (void)n_in; (void)out_size;
    const int*   input_ids = (const int*)  d_in[0];
    const int*   token_tt  = (const int*)  d_in[1];
    const int*   attn_mask = (const int*)  d_in[2];
    const int*   location  = (const int*)  d_in[3];
    const float* sense_emb = (const float*)d_in[4];
    const float* word_emb  = (const float*)d_in[5];
    const float* pos_emb   = (const float*)d_in[6];
    const float* type_emb  = (const float*)d_in[7];
    const float* emb_ln_g  = (const float*)d_in[8];
    const float* emb_ln_b  = (const float*)d_in[9];
    const float* Wq  = (const float*)d_in[10]; const float* bq  = (const float*)d_in[11];
    const float* Wk  = (const float*)d_in[12]; const float* bk  = (const float*)d_in[13];
    const float* Wv  = (const float*)d_in[14]; const float* bv  = (const float*)d_in[15];
    const float* Wo  = (const float*)d_in[16]; const float* bo  = (const float*)d_in[17];
    const float* ln1g= (const float*)d_in[18]; const float* ln1b= (const float*)d_in[19];
    const float* W1  = (const float*)d_in[20]; const float* b1  = (const float*)d_in[21];
    const float* W2  = (const float*)d_in[22]; const float* b2  = (const float*)d_in[23];
    const float* ln2g= (const float*)d_in[24]; const float* ln2b= (const float*)d_in[25];
    const float* attWq=(const float*)d_in[26]; const float* attWk=(const float*)d_in[27];
    float* out = (float*)d_out;

    float *x,*qkv,*a,*t,*h,*sk,*pq;
    float *wqkvT,*bqkv,*woT,*w1T,*w2T;
    cudaGetSymbolAddress((void**)&x,    g_x);
    cudaGetSymbolAddress((void**)&qkv,  g_qkv);
    cudaGetSymbolAddress((void**)&a,    g_a);
    cudaGetSymbolAddress((void**)&t,    g_t);
    cudaGetSymbolAddress((void**)&h,    g_h);
    cudaGetSymbolAddress((void**)&sk,   g_sk);
    cudaGetSymbolAddress((void**)&pq,   g_pq);
    cudaGetSymbolAddress((void**)&wqkvT,g_wqkvT);
    cudaGetSymbolAddress((void**)&bqkv, g_bqkv);
    cudaGetSymbolAddress((void**)&woT,  g_woT);
    cudaGetSymbolAddress((void**)&w1T,  g_w1T);
    cudaGetSymbolAddress((void**)&w2T,  g_w2T);

    cudaFuncSetAttribute(gemm_tf32_ldsm, cudaFuncAttributeMaxDynamicSharedMemorySize,
                         GSM_BYTES);

    /* transpose weights into n-major layouts; QKV fused into one [2304][768] */
    {
        dim3 thr(32, 8);
        dim3 gDD(D_/32,  D_/32,  L_);
        dim3 g1 (FF_/32, D_/32,  L_);
        dim3 g2 (D_/32,  FF_/32, L_);
        size_t sDD = (size_t)D_*D_, sQKV = (size_t)QKV_*D_, sDF = (size_t)D_*FF_;
        transpose_f32<<<gDD, thr>>>(Wq, wqkvT, D_, D_, sDD, sQKV, 0);
        transpose_f32<<<gDD, thr>>>(Wk, wqkvT, D_, D_, sDD, sQKV, D_);
        transpose_f32<<<gDD, thr>>>(Wv, wqkvT, D_, D_, sDD, sQKV, 2*D_);
        transpose_f32<<<gDD, thr>>>(Wo, woT, D_, D_, sDD, sDD, 0);
        transpose_f32<<<g1,  thr>>>(W1, w1T, D_, FF_, sDF, sDF, 0);
        transpose_f32<<<g2,  thr>>>(W2, w2T, FF_, D_, sDF, sDF, 0);
        concat_bias_kernel<<<(L_*QKV_ + 255)/256, 256>>>(bq, bk, bv, bqkv);
    }

    embed_ln_kernel<<<NT_, 256>>>(input_ids, token_tt, word_emb, pos_emb, type_emb,
                                  emb_ln_g, emb_ln_b, x);

    dim3 gD(D_/128,   NT_/128);  /* N=768  */
    dim3 gQ(QKV_/128, NT_/128);  /* N=2304 */
    dim3 gF(FF_/128,  NT_/128);  /* N=3072 */

    for (int l = 0; l < L_; l++) {
        size_t wDD = (size_t)l*D_*D_;
        size_t wDF = (size_t)l*D_*FF_;
        gemm_tf32_ldsm<<<gQ, 256, GSM_BYTES>>>(x, wqkvT + (size_t)l*QKV_*D_,
                                               bqkv + l*QKV_, nullptr,
                                               qkv, NT_, QKV_, D_, 0);
        attention_tc2<<<dim3(4, H_, B_), 128>>>(qkv, attn_mask, a);
        gemm_tf32_ldsm<<<gD, 256, GSM_BYTES>>>(a, woT + wDD, bo + l*D_, x,
                                               t, NT_, D_, D_, 0);
        ln_kernel<<<NT_, 256>>>(t, x, ln1g + l*D_, ln1b + l*D_);
        gemm_tf32_ldsm<<<gF, 256, GSM_BYTES>>>(x, w1T + wDF, b1 + l*FF_, nullptr,
                                               h, NT_, FF_, D_, 1);
        gemm_tf32_ldsm<<<gD, 256, GSM_BYTES>>>(h, w2T + wDF, b2 + l*D_, x,
                                               t, NT_, D_, FF_, 0);
        ln_kernel<<<NT_, 256>>>(t, x, ln2g + l*D_, ln2b + l*D_);
    }

    sense_proj_kernel<<<16, 256>>>(sense_emb, attWk, sk);
    pun_proj_kernel<<<8, 256>>>(x, location, attWq, pq);
    top2_kernel<<<B_, 64>>>(pq, sk, out);
}

// round 13
// speedup vs baseline: 1.0776x; 1.0776x over previous
#include <cuda_runtime.h>
#include <math.h>
#include <stdint.h>

#define L_  12
#define H_  12
#define D_  768
#define DH_ 64
#define FF_ 3072
#define B_  32
#define S_  256
#define NT_ (B_*S_)     /* 8192 tokens */
#define QKV_ (3*D_)     /* 2304 */

/* ---------------- scratch (device globals; no allocations) ---------------- */
__device__ float g_x[NT_*D_];
__device__ float g_qkv[(size_t)NT_*QKV_];
__device__ float g_a[NT_*D_];
__device__ float g_t[NT_*D_];
__device__ float g_h[(size_t)NT_*FF_];
__device__ float g_sk[64*64];
__device__ float g_pq[32*64];
/* transposed weights: [l][N][K] so GEMM B-operand is n-major */
__device__ float g_wqkvT[(size_t)L_*QKV_*D_];
__device__ float g_bqkv[L_*QKV_];
__device__ float g_woT[L_*D_*D_];
__device__ float g_w1T[(size_t)L_*D_*FF_];
__device__ float g_w2T[(size_t)L_*D_*FF_];

/* ------ tiled transpose: src[z][K][N] -> dst[z (dst_ls)][row_off + N][K] -- */
__global__ void transpose_f32(const float* __restrict__ src, float* __restrict__ dst,
                              int K, int N, size_t src_ls, size_t dst_ls, int row_off)
{
    __shared__ float tile[32][33];
    size_t soff = (size_t)blockIdx.z * src_ls;
    size_t doff = (size_t)blockIdx.z * dst_ls;
    int n0 = blockIdx.x * 32, k0 = blockIdx.y * 32;
    int tx = threadIdx.x, ty = threadIdx.y;
    #pragma unroll
    for (int i = 0; i < 32; i += 8)
        tile[ty + i][tx] = src[soff + (size_t)(k0 + ty + i) * N + n0 + tx];
    __syncthreads();
    #pragma unroll
    for (int i = 0; i < 32; i += 8)
        dst[doff + (size_t)(row_off + n0 + ty + i) * K + k0 + tx] = tile[tx][ty + i];
}

/* ---------------- concat QKV biases: [L][3*D] ---------------- */
__global__ void concat_bias_kernel(const float* __restrict__ bq, const float* __restrict__ bk,
                                   const float* __restrict__ bv, float* __restrict__ bqkv)
{
    int i = blockIdx.x*256 + threadIdx.x;
    if (i >= L_*QKV_) return;
    int l = i / QKV_, c = i % QKV_;
    float val = (c < D_) ? bq[l*D_ + c]
              : (c < 2*D_) ? bk[l*D_ + c - D_]
              : bv[l*D_ + c - 2*D_];
    bqkv[i] = val;
}

/* ---------------- block reduction (256 threads) ---------------- */
__device__ __forceinline__ float block_sum_256(float v, float* red) {
    int lane = threadIdx.x & 31, w = threadIdx.x >> 5;
    #pragma unroll
    for (int o = 16; o > 0; o >>= 1) v += __shfl_down_sync(0xffffffffu, v, o);
    if (lane == 0) red[w] = v;
    __syncthreads();
    if (w == 0) {
        float x = (lane < 8) ? red[lane] : 0.f;
        #pragma unroll
        for (int o = 4; o > 0; o >>= 1) x += __shfl_down_sync(0xffffffffu, x, o);
        if (lane == 0) red[32] = x;
    }
    __syncthreads();
    return red[32];
}

/* ---------------- embeddings + LayerNorm ---------------- */
__global__ void embed_ln_kernel(const int* __restrict__ ids, const int* __restrict__ tt,
                                const float* __restrict__ we, const float* __restrict__ pe,
                                const float* __restrict__ te, const float* __restrict__ g,
                                const float* __restrict__ b, float* __restrict__ x)
{
    int row = blockIdx.x;
    int s = row & (S_-1);
    int id = ids[row], t = tt[row];
    __shared__ float buf[D_];
    __shared__ float red[40];
    int tid = threadIdx.x;
    float ps = 0.f;
    #pragma unroll
    for (int i = 0; i < 3; i++) {
        int d = tid + i*256;
        float e = we[(size_t)id*D_ + d] + pe[s*D_ + d] + te[t*D_ + d];
        buf[d] = e; ps += e;
    }
    __syncthreads();
    float mean = block_sum_256(ps, red) * (1.f/D_);
    float pv = 0.f;
    #pragma unroll
    for (int i = 0; i < 3; i++) { int d = tid + i*256; float c = buf[d]-mean; pv += c*c; }
    float var = block_sum_256(pv, red) * (1.f/D_);
    float inv = rsqrtf(var + 1e-12f);
    #pragma unroll
    for (int i = 0; i < 3; i++) {
        int d = tid + i*256;
        x[(size_t)row*D_ + d] = (buf[d]-mean)*inv*g[d] + b[d];
    }
}

/* ---------------- residual add + LayerNorm (in-place on x) ---------------- */
__global__ void add_ln_kernel(float* __restrict__ x, const float* __restrict__ t,
                              const float* __restrict__ g, const float* __restrict__ b)
{
    int row = blockIdx.x;
    __shared__ float buf[D_];
    __shared__ float red[40];
    int tid = threadIdx.x;
    float ps = 0.f;
    #pragma unroll
    for (int i = 0; i < 3; i++) {
        int d = tid + i*256;
        float e = x[(size_t)row*D_ + d] + t[(size_t)row*D_ + d];
        buf[d] = e; ps += e;
    }
    __syncthreads();
    float mean = block_sum_256(ps, red) * (1.f/D_);
    float pv = 0.f;
    #pragma unroll
    for (int i = 0; i < 3; i++) { int d = tid + i*256; float c = buf[d]-mean; pv += c*c; }
    float var = block_sum_256(pv, red) * (1.f/D_);
    float inv = rsqrtf(var + 1e-12f);
    #pragma unroll
    for (int i = 0; i < 3; i++) {
        int d = tid + i*256;
        x[(size_t)row*D_ + d] = (buf[d]-mean)*inv*g[d] + b[d];
    }
}

/* ---------------- tf32 mma primitives ---------------- */
__device__ __forceinline__ void cpasync16(void* smem, const void* gmem) {
    uint32_t s = (uint32_t)__cvta_generic_to_shared(smem);
    asm volatile("cp.async.ca.shared.global [%0], [%1], 16;\n" :: "r"(s), "l"(gmem));
}
__device__ __forceinline__ void cp_commit() { asm volatile("cp.async.commit_group;\n"); }
__device__ __forceinline__ void cp_wait0()  { asm volatile("cp.async.wait_group 0;\n"); }

__device__ __forceinline__ void ldsm_x4(uint32_t* r, uint32_t saddr) {
    asm volatile("ldmatrix.sync.aligned.m8n8.x4.shared.b16 {%0,%1,%2,%3}, [%4];"
                 : "=r"(r[0]), "=r"(r[1]), "=r"(r[2]), "=r"(r[3]) : "r"(saddr));
}
__device__ __forceinline__ void mma_tf32(float* d, const uint32_t* a, const uint32_t* b) {
    asm volatile(
        "mma.sync.aligned.m16n8k8.row.col.f32.tf32.tf32.f32 "
        "{%0,%1,%2,%3}, {%4,%5,%6,%7}, {%8,%9}, {%0,%1,%2,%3};\n"
        : "+f"(d[0]), "+f"(d[1]), "+f"(d[2]), "+f"(d[3])
        : "r"(a[0]), "r"(a[1]), "r"(a[2]), "r"(a[3]), "r"(b[0]), "r"(b[1]));
}

/* ================= tf32 tensor-core GEMM with ldmatrix (128x128) ========= */
#define PAD 20   /* row stride in floats: ldmatrix phase covers all 32 banks */

__global__ __launch_bounds__(256, 2)
void gemm_tf32_ldsm(const float* __restrict__ A, const float* __restrict__ BT,
                    const float* __restrict__ bias, float* __restrict__ C,
                    int M, int N, int K, int gelu)
{
    __shared__ __align__(16) float As[2][128][PAD];
    __shared__ __align__(16) float Bt[2][128][PAD];

    const int tid  = threadIdx.x;
    const int brow = blockIdx.y * 128;
    const int bcol = blockIdx.x * 128;
    const int lane = tid & 31;
    const int wid  = tid >> 5;
    const int g    = lane >> 2;
    const int tg   = lane & 3;
    const int wm   = (wid & 1) * 64;
    const int wn   = (wid >> 1) * 32;

    const int a_m = lane & 15;
    const int a_k = (lane >> 4) << 2;
    const int b_n = (lane & 7) + ((lane >> 4) << 3);
    const int b_k = ((lane >> 3) & 1) << 2;

    float acc[4][4][4];
    #pragma unroll
    for (int mt = 0; mt < 4; mt++)
        #pragma unroll
        for (int nt = 0; nt < 4; nt++)
            #pragma unroll
            for (int i = 0; i < 4; i++) acc[mt][nt][i] = 0.f;

    const int lr = tid >> 2, lc = (tid & 3) << 2;

    #define LOAD_STAGE(buf, k0) do {                                                   \
        cpasync16(&As[buf][lr   ][lc], A  + (size_t)(brow + lr     )*K + (k0) + lc);    \
        cpasync16(&As[buf][lr+64][lc], A  + (size_t)(brow + lr + 64)*K + (k0) + lc);    \
        cpasync16(&Bt[buf][lr   ][lc], BT + (size_t)(bcol + lr     )*K + (k0) + lc);    \
        cpasync16(&Bt[buf][lr+64][lc], BT + (size_t)(bcol + lr + 64)*K + (k0) + lc);    \
        cp_commit();                                                                   \
    } while (0)

    LOAD_STAGE(0, 0);

    const int nk = K >> 4;
    for (int it = 0; it < nk; it++) {
        cp_wait0();
        __syncthreads();
        const int cur = it & 1;
        if (it + 1 < nk) LOAD_STAGE(cur ^ 1, (it + 1) << 4);

        #pragma unroll
        for (int kk = 0; kk < 16; kk += 8) {
            uint32_t afr[4][4];
            #pragma unroll
            for (int mt = 0; mt < 4; mt++) {
                uint32_t addr = (uint32_t)__cvta_generic_to_shared(
                    &As[cur][wm + mt*16 + a_m][kk + a_k]);
                ldsm_x4(afr[mt], addr);
            }
            uint32_t bfr[2][4];
            #pragma unroll
            for (int np = 0; np < 2; np++) {
                uint32_t addr = (uint32_t)__cvta_generic_to_shared(
                    &Bt[cur][wn + np*16 + b_n][kk + b_k]);
                ldsm_x4(bfr[np], addr);
            }
            #pragma unroll
            for (int mt = 0; mt < 4; mt++)
                #pragma unroll
                for (int nt = 0; nt < 4; nt++)
                    mma_tf32(acc[mt][nt], afr[mt], &bfr[nt >> 1][(nt & 1) * 2]);
        }
    }

    #pragma unroll
    for (int mt = 0; mt < 4; mt++) {
        #pragma unroll
        for (int nt = 0; nt < 4; nt++) {
            int row0 = brow + wm + mt*16 + g;
            int col  = bcol + wn + nt*8 + tg*2;
            float b0 = bias[col], b1 = bias[col + 1];
            float c0 = acc[mt][nt][0] + b0;
            float c1 = acc[mt][nt][1] + b1;
            float c2 = acc[mt][nt][2] + b0;
            float c3 = acc[mt][nt][3] + b1;
            if (gelu) {
                c0 = 0.5f*c0*(1.f + erff(c0*0.70710678118654752f));
                c1 = 0.5f*c1*(1.f + erff(c1*0.70710678118654752f));
                c2 = 0.5f*c2*(1.f + erff(c2*0.70710678118654752f));
                c3 = 0.5f*c3*(1.f + erff(c3*0.70710678118654752f));
            }
            *(float2*)(C + (size_t)row0*N + col)       = make_float2(c0, c1);
            *(float2*)(C + (size_t)(row0 + 8)*N + col) = make_float2(c2, c3);
        }
    }
}

/* ===== 64x128-tile variant (for N=768 GEMMs: better wave fill) ===== */
__global__ __launch_bounds__(256)
void gemm64_tf32_ldsm(const float* __restrict__ A, const float* __restrict__ BT,
                      const float* __restrict__ bias, float* __restrict__ C,
                      int M, int N, int K, int gelu)
{
    __shared__ __align__(16) float As[2][64][PAD];
    __shared__ __align__(16) float Bt[2][128][PAD];

    const int tid  = threadIdx.x;
    const int brow = blockIdx.y * 64;
    const int bcol = blockIdx.x * 128;
    const int lane = tid & 31;
    const int wid  = tid >> 5;
    const int g    = lane >> 2;
    const int tg   = lane & 3;
    const int wm   = (wid & 1) * 32;
    const int wn   = (wid >> 1) * 32;

    const int a_m = lane & 15;
    const int a_k = (lane >> 4) << 2;
    const int b_n = (lane & 7) + ((lane >> 4) << 3);
    const int b_k = ((lane >> 3) & 1) << 2;

    float acc[2][4][4];
    #pragma unroll
    for (int mt = 0; mt < 2; mt++)
        #pragma unroll
        for (int nt = 0; nt < 4; nt++)
            #pragma unroll
            for (int i = 0; i < 4; i++) acc[mt][nt][i] = 0.f;

    const int ar = tid >> 2, ac = (tid & 3) << 2;   /* A: 64 rows, 1 chunk/thread */
    const int lr = tid >> 2, lc = (tid & 3) << 2;   /* B: 128 rows, 2 chunks/thread */

    #define LOAD_STAGE64(buf, k0) do {                                                 \
        cpasync16(&As[buf][ar   ][ac], A  + (size_t)(brow + ar     )*K + (k0) + ac);    \
        cpasync16(&Bt[buf][lr   ][lc], BT + (size_t)(bcol + lr     )*K + (k0) + lc);    \
        cpasync16(&Bt[buf][lr+64][lc], BT + (size_t)(bcol + lr + 64)*K + (k0) + lc);    \
        cp_commit();                                                                   \
    } while (0)

    LOAD_STAGE64(0, 0);

    const int nk = K >> 4;
    for (int it = 0; it < nk; it++) {
        cp_wait0();
        __syncthreads();
        const int cur = it & 1;
        if (it + 1 < nk) LOAD_STAGE64(cur ^ 1, (it + 1) << 4);

        #pragma unroll
        for (int kk = 0; kk < 16; kk += 8) {
            uint32_t afr[2][4];
            #pragma unroll
            for (int mt = 0; mt < 2; mt++) {
                uint32_t addr = (uint32_t)__cvta_generic_to_shared(
                    &As[cur][wm + mt*16 + a_m][kk + a_k]);
                ldsm_x4(afr[mt], addr);
            }
            uint32_t bfr[2][4];
            #pragma unroll
            for (int np = 0; np < 2; np++) {
                uint32_t addr = (uint32_t)__cvta_generic_to_shared(
                    &Bt[cur][wn + np*16 + b_n][kk + b_k]);
                ldsm_x4(bfr[np], addr);
            }
            #pragma unroll
            for (int mt = 0; mt < 2; mt++)
                #pragma unroll
                for (int nt = 0; nt < 4; nt++)
                    mma_tf32(acc[mt][nt], afr[mt], &bfr[nt >> 1][(nt & 1) * 2]);
        }
    }

    #pragma unroll
    for (int mt = 0; mt < 2; mt++) {
        #pragma unroll
        for (int nt = 0; nt < 4; nt++) {
            int row0 = brow + wm + mt*16 + g;
            int col  = bcol + wn + nt*8 + tg*2;
            float b0 = bias[col], b1 = bias[col + 1];
            float c0 = acc[mt][nt][0] + b0;
            float c1 = acc[mt][nt][1] + b1;
            float c2 = acc[mt][nt][2] + b0;
            float c3 = acc[mt][nt][3] + b1;
            if (gelu) {
                c0 = 0.5f*c0*(1.f + erff(c0*0.70710678118654752f));
                c1 = 0.5f*c1*(1.f + erff(c1*0.70710678118654752f));
                c2 = 0.5f*c2*(1.f + erff(c2*0.70710678118654752f));
                c3 = 0.5f*c3*(1.f + erff(c3*0.70710678118654752f));
            }
            *(float2*)(C + (size_t)row0*N + col)       = make_float2(c0, c1);
            *(float2*)(C + (size_t)(row0 + 8)*N + col) = make_float2(c2, c3);
        }
    }
}

/* ============ tensor-core flash attention v2 (tf32, low-reg) ============ */
__global__ __launch_bounds__(128)
void attention_tc2(const float* __restrict__ qkv, const int* __restrict__ mask,
                   float* __restrict__ o)
{
    __shared__ __align__(16) float Ks[2][32][68];
    __shared__ __align__(16) float Vt[2][64][36];
    __shared__ __align__(16) float Ps[4][16][36];
    __shared__ float mb[S_];

    const int qq = blockIdx.x, h = blockIdx.y, b = blockIdx.z;
    const int tid = threadIdx.x, lane = tid & 31, w = tid >> 5;
    const int g = lane >> 2, tg = lane & 3;
    const int a_m = lane & 15;
    const int a_k = (lane >> 4) << 2;
    const int b_n = (lane & 7) + ((lane >> 4) << 3);
    const int b_k = ((lane >> 3) & 1) << 2;

    const size_t baseq = (size_t)b * S_ * QKV_ + (size_t)h * DH_;
    const size_t basek = baseq + D_;
    const size_t basev = baseq + 2*D_;
    const size_t baseo = (size_t)b * S_ * D_ + (size_t)h * DH_;
    const int q0 = qq*64 + w*16;

    mb[tid]       = mask[b*S_ + tid]       ? 0.f : -10000.f;
    mb[tid + 128] = mask[b*S_ + tid + 128] ? 0.f : -10000.f;

    float qf[8][4];
    #pragma unroll
    for (int kt = 0; kt < 8; kt++) {
        const float* qp = qkv + baseq + (size_t)(q0 + g)*QKV_ + kt*8 + tg;
        qf[kt][0] = 0.125f * qp[0];
        qf[kt][1] = 0.125f * qp[(size_t)8*QKV_];
        qf[kt][2] = 0.125f * qp[4];
        qf[kt][3] = 0.125f * qp[(size_t)8*QKV_ + 4];
    }

    float O[8][4];
    #pragma unroll
    for (int nt = 0; nt < 8; nt++)
        #pragma unroll
        for (int i = 0; i < 4; i++) O[nt][i] = 0.f;
    float mrow[2] = {-1e30f, -1e30f};
    float lrow[2] = {0.f, 0.f};

    const int kr = tid >> 2, kc = (tid & 3) << 2;
    const int vr = tid >> 2, vcb = (tid & 3) << 4;

    auto att_load_k = [&](int buf, int kv0) {
        cpasync16(&Ks[buf][kr][kc     ], qkv + basek + (size_t)(kv0 + kr)*QKV_ + kc     );
        cpasync16(&Ks[buf][kr][kc + 16], qkv + basek + (size_t)(kv0 + kr)*QKV_ + kc + 16);
        cpasync16(&Ks[buf][kr][kc + 32], qkv + basek + (size_t)(kv0 + kr)*QKV_ + kc + 32);
        cpasync16(&Ks[buf][kr][kc + 48], qkv + basek + (size_t)(kv0 + kr)*QKV_ + kc + 48);
        cp_commit();
    };

    float vreg[16];
    auto att_ldg_v = [&](int kv0) {
        #pragma unroll
        for (int j = 0; j < 4; j++)
            *(float4*)&vreg[4*j] =
                *(const float4*)(qkv + basev + (size_t)(kv0 + vr)*QKV_ + vcb + 4*j);
    };

    auto att_sts_v = [&](int buf) {
        #pragma unroll
        for (int s = 0; s < 16; s++) {
            int jj = (s + ((tid & 3) << 2)) & 15;
            Vt[buf][vcb + jj][vr] = vreg[jj];
        }
    };

    att_load_k(0, 0);
    att_ldg_v(0);
    att_sts_v(0);

    for (int it = 0; it < S_/32; it++) {
        cp_wait0();
        __syncthreads();
        const int cur = it & 1;
        const int kv0 = it*32;
        if (it + 1 < S_/32) {
            att_load_k(cur ^ 1, kv0 + 32);
            att_ldg_v(kv0 + 32);
        }

        float sc[4][4];
        #pragma unroll
        for (int nt = 0; nt < 4; nt++)
            #pragma unroll
            for (int i = 0; i < 4; i++) sc[nt][i] = 0.f;
        #pragma unroll
        for (int kt = 0; kt < 8; kt++) {
            uint32_t bfr[2][4];
            #pragma unroll
            for (int np = 0; np < 2; np++) {
                uint32_t addr = (uint32_t)__cvta_generic_to_shared(
                    &Ks[cur][np*16 + b_n][kt*8 + b_k]);
                ldsm_x4(bfr[np], addr);
            }
            #pragma unroll
            for (int nt = 0; nt < 4; nt++)
                mma_tf32(sc[nt], (const uint32_t*)qf[kt],
                         &bfr[nt >> 1][(nt & 1) * 2]);
        }

        #pragma unroll
        for (int nt = 0; nt < 4; nt++) {
            float m0 = mb[kv0 + nt*8 + 2*tg], m1 = mb[kv0 + nt*8 + 2*tg + 1];
            sc[nt][0] += m0; sc[nt][1] += m1;
            sc[nt][2] += m0; sc[nt][3] += m1;
        }
        #pragma unroll
        for (int rh = 0; rh < 2; rh++) {
            float mx = -1e30f;
            #pragma unroll
            for (int nt = 0; nt < 4; nt++)
                mx = fmaxf(mx, fmaxf(sc[nt][2*rh], sc[nt][2*rh+1]));
            mx = fmaxf(mx, __shfl_xor_sync(0xffffffffu, mx, 1));
            mx = fmaxf(mx, __shfl_xor_sync(0xffffffffu, mx, 2));
            float nm = fmaxf(mrow[rh], mx);
            float scale = __expf(mrow[rh] - nm);
            mrow[rh] = nm;
            float rs = 0.f;
            #pragma unroll
            for (int nt = 0; nt < 4; nt++) {
                float e0 = __expf(sc[nt][2*rh]   - nm);
                float e1 = __expf(sc[nt][2*rh+1] - nm);
                sc[nt][2*rh] = e0; sc[nt][2*rh+1] = e1;
                rs += e0 + e1;
            }
            rs += __shfl_xor_sync(0xffffffffu, rs, 1);
            rs += __shfl_xor_sync(0xffffffffu, rs, 2);
            lrow[rh] = lrow[rh]*scale + rs;
            #pragma unroll
            for (int nt = 0; nt < 8; nt++) {
                O[nt][2*rh]   *= scale;
                O[nt][2*rh+1] *= scale;
            }
        }
        #pragma unroll
        for (int nt = 0; nt < 4; nt++) {
            *(float2*)&Ps[w][g    ][nt*8 + 2*tg] = make_float2(sc[nt][0], sc[nt][1]);
            *(float2*)&Ps[w][g + 8][nt*8 + 2*tg] = make_float2(sc[nt][2], sc[nt][3]);
        }
        __syncwarp();

        #pragma unroll
        for (int kt = 0; kt < 4; kt++) {
            uint32_t pf[4];
            {
                uint32_t addr = (uint32_t)__cvta_generic_to_shared(
                    &Ps[w][a_m][kt*8 + a_k]);
                ldsm_x4(pf, addr);
            }
            uint32_t bfr[4][4];
            #pragma unroll
            for (int np = 0; np < 4; np++) {
                uint32_t addr = (uint32_t)__cvta_generic_to_shared(
                    &Vt[cur][np*16 + b_n][kt*8 + b_k]);
                ldsm_x4(bfr[np], addr);
            }
            #pragma unroll
            for (int nt = 0; nt < 8; nt++)
                mma_tf32(O[nt], pf, &bfr[nt >> 1][(nt & 1) * 2]);
        }

        if (it + 1 < S_/32) att_sts_v(cur ^ 1);
    }

    float inv0 = 1.f / lrow[0];
    float inv1 = 1.f / lrow[1];
    #pragma unroll
    for (int nt = 0; nt < 8; nt++) {
        int col = nt*8 + 2*tg;
        *(float2*)(o + baseo + (size_t)(q0 + g)*D_ + col) =
            make_float2(O[nt][0]*inv0, O[nt][1]*inv0);
        *(float2*)(o + baseo + (size_t)(q0 + g + 8)*D_ + col) =
            make_float2(O[nt][2]*inv1, O[nt][3]*inv1);
    }
}

/* ---------------- sense head ---------------- */
__global__ void sense_proj_kernel(const float* __restrict__ sense_emb,
                                  const float* __restrict__ att_Wk, float* __restrict__ sk)
{
    int idx = blockIdx.x*256 + threadIdx.x;
    int j = idx >> 6, a = idx & 63;
    float s = 0.f;
    for (int d = 0; d < D_; d++)
        s += sense_emb[(size_t)j*D_ + d] * att_Wk[(size_t)d*64 + a];
    sk[idx] = s;
}

__global__ void pun_proj_kernel(const float* __restrict__ x, const int* __restrict__ loc,
                                const float* __restrict__ att_Wq, float* __restrict__ pq)
{
    int idx = blockIdx.x*256 + threadIdx.x;
    int b = idx >> 6, a = idx & 63;
    int row = b*S_ + loc[b];
    float s = 0.f;
    for (int d = 0; d < D_; d++)
        s += x[(size_t)row*D_ + d] * att_Wq[(size_t)d*64 + a];
    pq[idx] = s;
}

__global__ void top2_kernel(const float* __restrict__ pq, const float* __restrict__ sk,
                            float* __restrict__ out)
{
    int b = blockIdx.x, j = threadIdx.x;
    __shared__ float sc[64];
    float s = 0.f;
    #pragma unroll 8
    for (int a = 0; a < 64; a++) s += pq[b*64 + a] * sk[j*64 + a];
    sc[j] = s * 0.125f;
    __syncthreads();
    if (j == 0) {
        int i1 = 0; float v1 = sc[0];
        for (int i = 1; i < 64; i++) if (sc[i] > v1) { v1 = sc[i]; i1 = i; }
        int i2 = -1; float v2 = -1e30f;
        for (int i = 0; i < 64; i++) if (i != i1 && sc[i] > v2) { v2 = sc[i]; i2 = i; }
        out[b*2 + 0] = (float)i1;
        out[b*2 + 1] = (float)i2;
    }
}

/* ---------------- launch ---------------- */
extern "C" void kernel_launch(void* const* d_in, const int* in_sizes, int n_in,
                              void* d_out, int out_size)
{
    (void)in_sizes; (void)n_in; (void)out_size;
    const int*   input_ids = (const int*)  d_in[0];
    const int*   token_tt  = (const int*)  d_in[1];
    const int*   attn_mask = (const int*)  d_in[2];
    const int*   location  = (const int*)  d_in[3];
    const float* sense_emb = (const float*)d_in[4];
    const float* word_emb  = (const float*)d_in[5];
    const float* pos_emb   = (const float*)d_in[6];
    const float* type_emb  = (const float*)d_in[7];
    const float* emb_ln_g  = (const float*)d_in[8];
    const float* emb_ln_b  = (const float*)d_in[9];
    const float* Wq  = (const float*)d_in[10]; const float* bq  = (const float*)d_in[11];
    const float* Wk  = (const float*)d_in[12]; const float* bk  = (const float*)d_in[13];
    const float* Wv  = (const float*)d_in[14]; const float* bv  = (const float*)d_in[15];
    const float* Wo  = (const float*)d_in[16]; const float* bo  = (const float*)d_in[17];
    const float* ln1g= (const float*)d_in[18]; const float* ln1b= (const float*)d_in[19];
    const float* W1  = (const float*)d_in[20]; const float* b1  = (const float*)d_in[21];
    const float* W2  = (const float*)d_in[22]; const float* b2  = (const float*)d_in[23];
    const float* ln2g= (const float*)d_in[24]; const float* ln2b= (const float*)d_in[25];
    const float* attWq=(const float*)d_in[26]; const float* attWk=(const float*)d_in[27];
    float* out = (float*)d_out;

    float *x,*qkv,*a,*t,*h,*sk,*pq;
    float *wqkvT,*bqkv,*woT,*w1T,*w2T;
    cudaGetSymbolAddress((void**)&x,    g_x);
    cudaGetSymbolAddress((void**)&qkv,  g_qkv);
    cudaGetSymbolAddress((void**)&a,    g_a);
    cudaGetSymbolAddress((void**)&t,    g_t);
    cudaGetSymbolAddress((void**)&h,    g_h);
    cudaGetSymbolAddress((void**)&sk,   g_sk);
    cudaGetSymbolAddress((void**)&pq,   g_pq);
    cudaGetSymbolAddress((void**)&wqkvT,g_wqkvT);
    cudaGetSymbolAddress((void**)&bqkv, g_bqkv);
    cudaGetSymbolAddress((void**)&woT,  g_woT);
    cudaGetSymbolAddress((void**)&w1T,  g_w1T);
    cudaGetSymbolAddress((void**)&w2T,  g_w2T);

    /* transpose weights into n-major layouts; QKV fused into one [2304][768] */
    {
        dim3 thr(32, 8);
        dim3 gDD(D_/32,  D_/32,  L_);
        dim3 g1 (FF_/32, D_/32,  L_);
        dim3 g2 (D_/32,  FF_/32, L_);
        size_t sDD = (size_t)D_*D_, sQKV = (size_t)QKV_*D_, sDF = (size_t)D_*FF_;
        transpose_f32<<<gDD, thr>>>(Wq, wqkvT, D_, D_, sDD, sQKV, 0);
        transpose_f32<<<gDD, thr>>>(Wk, wqkvT, D_, D_, sDD, sQKV, D_);
        transpose_f32<<<gDD, thr>>>(Wv, wqkvT, D_, D_, sDD, sQKV, 2*D_);
        transpose_f32<<<gDD, thr>>>(Wo, woT, D_, D_, sDD, sDD, 0);
        transpose_f32<<<g1,  thr>>>(W1, w1T, D_, FF_, sDF, sDF, 0);
        transpose_f32<<<g2,  thr>>>(W2, w2T, FF_, D_, sDF, sDF, 0);
        concat_bias_kernel<<<(L_*QKV_ + 255)/256, 256>>>(bq, bk, bv, bqkv);
    }

    embed_ln_kernel<<<NT_, 256>>>(input_ids, token_tt, word_emb, pos_emb, type_emb,
                                  emb_ln_g, emb_ln_b, x);

    dim3 gQ(QKV_/128, NT_/128);  /* N=2304, 128x128 tiles */
    dim3 gF(FF_/128,  NT_/128);  /* N=3072, 128x128 tiles */
    dim3 gD64(D_/128, NT_/64);   /* N=768,  64x128 tiles -> 768 CTAs */

    for (int l = 0; l < L_; l++) {
        size_t wDD = (size_t)l*D_*D_;
        size_t wDF = (size_t)l*D_*FF_;
        gemm_tf32_ldsm<<<gQ, 256>>>(x, wqkvT + (size_t)l*QKV_*D_, bqkv + l*QKV_,
                                    qkv, NT_, QKV_, D_, 0);
        attention_tc2<<<dim3(4, H_, B_), 128>>>(qkv, attn_mask, a);
        gemm64_tf32_ldsm<<<gD64, 256>>>(a, woT + wDD, bo + l*D_, t, NT_, D_, D_, 0);
        add_ln_kernel<<<NT_, 256>>>(x, t, ln1g + l*D_, ln1b + l*D_);
        gemm_tf32_ldsm<<<gF, 256>>>(x, w1T + wDF, b1 + l*FF_, h, NT_, FF_, D_, 1);
        gemm64_tf32_ldsm<<<gD64, 256>>>(h, w2T + wDF, b2 + l*D_, t, NT_, D_, FF_, 0);
        add_ln_kernel<<<NT_, 256>>>(x, t, ln2g + l*D_, ln2b + l*D_);
    }

    sense_proj_kernel<<<16, 256>>>(sense_emb, attWk, sk);
    pun_proj_kernel<<<8, 256>>>(x, location, attWq, pq);
    top2_kernel<<<B_, 64>>>(pq, sk, out);
}

// round 14
// speedup vs baseline: 1.1324x; 1.0509x over previous
#include <cuda_runtime.h>
#include <math.h>
#include <stdint.h>

#define L_  12
#define H_  12
#define D_  768
#define DH_ 64
#define FF_ 3072
#define B_  32
#define S_  256
#define NT_ (B_*S_)     /* 8192 tokens */
#define QKV_ (3*D_)     /* 2304 */

/* ---------------- scratch (device globals; no allocations) ---------------- */
__device__ float g_x[NT_*D_];
__device__ float g_qkv[(size_t)NT_*QKV_];
__device__ float g_a[NT_*D_];
__device__ float g_t[NT_*D_];
__device__ float g_h[(size_t)NT_*FF_];
__device__ float g_sk[64*64];
__device__ float g_pq[32*64];
/* transposed weights: [l][N][K] so GEMM B-operand is n-major */
__device__ float g_wqkvT[(size_t)L_*QKV_*D_];
__device__ float g_bqkv[L_*QKV_];
__device__ float g_woT[L_*D_*D_];
__device__ float g_w1T[(size_t)L_*D_*FF_];
__device__ float g_w2T[(size_t)L_*D_*FF_];

/* ------ tiled transpose: src[z][K][N] -> dst[z (dst_ls)][row_off + N][K] -- */
__global__ void transpose_f32(const float* __restrict__ src, float* __restrict__ dst,
                              int K, int N, size_t src_ls, size_t dst_ls, int row_off)
{
    __shared__ float tile[32][33];
    size_t soff = (size_t)blockIdx.z * src_ls;
    size_t doff = (size_t)blockIdx.z * dst_ls;
    int n0 = blockIdx.x * 32, k0 = blockIdx.y * 32;
    int tx = threadIdx.x, ty = threadIdx.y;
    #pragma unroll
    for (int i = 0; i < 32; i += 8)
        tile[ty + i][tx] = src[soff + (size_t)(k0 + ty + i) * N + n0 + tx];
    __syncthreads();
    #pragma unroll
    for (int i = 0; i < 32; i += 8)
        dst[doff + (size_t)(row_off + n0 + ty + i) * K + k0 + tx] = tile[tx][ty + i];
}

/* ---------------- concat QKV biases: [L][3*D] ---------------- */
__global__ void concat_bias_kernel(const float* __restrict__ bq, const float* __restrict__ bk,
                                   const float* __restrict__ bv, float* __restrict__ bqkv)
{
    int i = blockIdx.x*256 + threadIdx.x;
    if (i >= L_*QKV_) return;
    int l = i / QKV_, c = i % QKV_;
    float val = (c < D_) ? bq[l*D_ + c]
              : (c < 2*D_) ? bk[l*D_ + c - D_]
              : bv[l*D_ + c - 2*D_];
    bqkv[i] = val;
}

/* ---------------- block reduction (192 threads = 6 warps) ---------------- */
__device__ __forceinline__ float block_sum_192(float v, float* red) {
    int lane = threadIdx.x & 31, w = threadIdx.x >> 5;
    #pragma unroll
    for (int o = 16; o > 0; o >>= 1) v += __shfl_down_sync(0xffffffffu, v, o);
    if (lane == 0) red[w] = v;
    __syncthreads();
    if (w == 0) {
        float x = (lane < 6) ? red[lane] : 0.f;
        #pragma unroll
        for (int o = 4; o > 0; o >>= 1) x += __shfl_down_sync(0xffffffffu, x, o);
        if (lane == 0) red[8] = x;
    }
    __syncthreads();
    return red[8];
}

/* ---------------- embeddings + LayerNorm (float4, 192 thr/row) ----------- */
__global__ void embed_ln_kernel(const int* __restrict__ ids, const int* __restrict__ tt,
                                const float* __restrict__ we, const float* __restrict__ pe,
                                const float* __restrict__ te, const float* __restrict__ g,
                                const float* __restrict__ b, float* __restrict__ x)
{
    int row = blockIdx.x;
    int s = row & (S_-1);
    int id = ids[row], t = tt[row];
    __shared__ float red[12];
    int d4 = threadIdx.x;                   /* float4 index, 0..191 */

    float4 wv = ((const float4*)(we + (size_t)id*D_))[d4];
    float4 pv = ((const float4*)(pe + (size_t)s*D_))[d4];
    float4 tv = ((const float4*)(te + (size_t)t*D_))[d4];
    float4 e = make_float4(wv.x+pv.x+tv.x, wv.y+pv.y+tv.y,
                           wv.z+pv.z+tv.z, wv.w+pv.w+tv.w);
    float ps = e.x + e.y + e.z + e.w;
    float mean = block_sum_192(ps, red) * (1.f/D_);
    float4 c = make_float4(e.x-mean, e.y-mean, e.z-mean, e.w-mean);
    float pvr = c.x*c.x + c.y*c.y + c.z*c.z + c.w*c.w;
    float var = block_sum_192(pvr, red) * (1.f/D_);
    float inv = rsqrtf(var + 1e-12f);
    float4 gv = ((const float4*)g)[d4];
    float4 bv = ((const float4*)b)[d4];
    float4 o = make_float4(c.x*inv*gv.x + bv.x, c.y*inv*gv.y + bv.y,
                           c.z*inv*gv.z + bv.z, c.w*inv*gv.w + bv.w);
    ((float4*)(x + (size_t)row*D_))[d4] = o;
}

/* --------- residual add + LayerNorm (float4, 192 thr/row, in-place) ------ */
__global__ void add_ln_kernel(float* __restrict__ x, const float* __restrict__ t,
                              const float* __restrict__ g, const float* __restrict__ b)
{
    int row = blockIdx.x;
    __shared__ float red[12];
    int d4 = threadIdx.x;                   /* 0..191 */

    float4 xv = ((const float4*)(x + (size_t)row*D_))[d4];
    float4 tv = ((const float4*)(t + (size_t)row*D_))[d4];
    float4 e = make_float4(xv.x+tv.x, xv.y+tv.y, xv.z+tv.z, xv.w+tv.w);
    float ps = e.x + e.y + e.z + e.w;
    float mean = block_sum_192(ps, red) * (1.f/D_);
    float4 c = make_float4(e.x-mean, e.y-mean, e.z-mean, e.w-mean);
    float pvr = c.x*c.x + c.y*c.y + c.z*c.z + c.w*c.w;
    float var = block_sum_192(pvr, red) * (1.f/D_);
    float inv = rsqrtf(var + 1e-12f);
    float4 gv = ((const float4*)g)[d4];
    float4 bv = ((const float4*)b)[d4];
    float4 o = make_float4(c.x*inv*gv.x + bv.x, c.y*inv*gv.y + bv.y,
                           c.z*inv*gv.z + bv.z, c.w*inv*gv.w + bv.w);
    ((float4*)(x + (size_t)row*D_))[d4] = o;
}

/* ---------------- tf32 mma primitives ---------------- */
__device__ __forceinline__ void cpasync16(void* smem, const void* gmem) {
    uint32_t s = (uint32_t)__cvta_generic_to_shared(smem);
    asm volatile("cp.async.ca.shared.global [%0], [%1], 16;\n" :: "r"(s), "l"(gmem));
}
__device__ __forceinline__ void cp_commit() { asm volatile("cp.async.commit_group;\n"); }
__device__ __forceinline__ void cp_wait0()  { asm volatile("cp.async.wait_group 0;\n"); }

__device__ __forceinline__ void ldsm_x4(uint32_t* r, uint32_t saddr) {
    asm volatile("ldmatrix.sync.aligned.m8n8.x4.shared.b16 {%0,%1,%2,%3}, [%4];"
                 : "=r"(r[0]), "=r"(r[1]), "=r"(r[2]), "=r"(r[3]) : "r"(saddr));
}
__device__ __forceinline__ void mma_tf32(float* d, const uint32_t* a, const uint32_t* b) {
    asm volatile(
        "mma.sync.aligned.m16n8k8.row.col.f32.tf32.tf32.f32 "
        "{%0,%1,%2,%3}, {%4,%5,%6,%7}, {%8,%9}, {%0,%1,%2,%3};\n"
        : "+f"(d[0]), "+f"(d[1]), "+f"(d[2]), "+f"(d[3])
        : "r"(a[0]), "r"(a[1]), "r"(a[2]), "r"(a[3]), "r"(b[0]), "r"(b[1]));
}

/* ================= tf32 tensor-core GEMM with ldmatrix (128x128) ========= */
#define PAD 20   /* row stride in floats: ldmatrix phase covers all 32 banks */

__global__ __launch_bounds__(256, 2)
void gemm_tf32_ldsm(const float* __restrict__ A, const float* __restrict__ BT,
                    const float* __restrict__ bias, float* __restrict__ C,
                    int M, int N, int K, int gelu)
{
    __shared__ __align__(16) float As[2][128][PAD];
    __shared__ __align__(16) float Bt[2][128][PAD];

    const int tid  = threadIdx.x;
    const int brow = blockIdx.y * 128;
    const int bcol = blockIdx.x * 128;
    const int lane = tid & 31;
    const int wid  = tid >> 5;
    const int g    = lane >> 2;
    const int tg   = lane & 3;
    const int wm   = (wid & 1) * 64;
    const int wn   = (wid >> 1) * 32;

    const int a_m = lane & 15;
    const int a_k = (lane >> 4) << 2;
    const int b_n = (lane & 7) + ((lane >> 4) << 3);
    const int b_k = ((lane >> 3) & 1) << 2;

    float acc[4][4][4];
    #pragma unroll
    for (int mt = 0; mt < 4; mt++)
        #pragma unroll
        for (int nt = 0; nt < 4; nt++)
            #pragma unroll
            for (int i = 0; i < 4; i++) acc[mt][nt][i] = 0.f;

    const int lr = tid >> 2, lc = (tid & 3) << 2;

    #define LOAD_STAGE(buf, k0) do {                                                   \
        cpasync16(&As[buf][lr   ][lc], A  + (size_t)(brow + lr     )*K + (k0) + lc);    \
        cpasync16(&As[buf][lr+64][lc], A  + (size_t)(brow + lr + 64)*K + (k0) + lc);    \
        cpasync16(&Bt[buf][lr   ][lc], BT + (size_t)(bcol + lr     )*K + (k0) + lc);    \
        cpasync16(&Bt[buf][lr+64][lc], BT + (size_t)(bcol + lr + 64)*K + (k0) + lc);    \
        cp_commit();                                                                   \
    } while (0)

    LOAD_STAGE(0, 0);

    const int nk = K >> 4;
    for (int it = 0; it < nk; it++) {
        cp_wait0();
        __syncthreads();
        const int cur = it & 1;
        if (it + 1 < nk) LOAD_STAGE(cur ^ 1, (it + 1) << 4);

        #pragma unroll
        for (int kk = 0; kk < 16; kk += 8) {
            uint32_t afr[4][4];
            #pragma unroll
            for (int mt = 0; mt < 4; mt++) {
                uint32_t addr = (uint32_t)__cvta_generic_to_shared(
                    &As[cur][wm + mt*16 + a_m][kk + a_k]);
                ldsm_x4(afr[mt], addr);
            }
            uint32_t bfr[2][4];
            #pragma unroll
            for (int np = 0; np < 2; np++) {
                uint32_t addr = (uint32_t)__cvta_generic_to_shared(
                    &Bt[cur][wn + np*16 + b_n][kk + b_k]);
                ldsm_x4(bfr[np], addr);
            }
            #pragma unroll
            for (int mt = 0; mt < 4; mt++)
                #pragma unroll
                for (int nt = 0; nt < 4; nt++)
                    mma_tf32(acc[mt][nt], afr[mt], &bfr[nt >> 1][(nt & 1) * 2]);
        }
    }

    #pragma unroll
    for (int mt = 0; mt < 4; mt++) {
        #pragma unroll
        for (int nt = 0; nt < 4; nt++) {
            int row0 = brow + wm + mt*16 + g;
            int col  = bcol + wn + nt*8 + tg*2;
            float b0 = bias[col], b1 = bias[col + 1];
            float c0 = acc[mt][nt][0] + b0;
            float c1 = acc[mt][nt][1] + b1;
            float c2 = acc[mt][nt][2] + b0;
            float c3 = acc[mt][nt][3] + b1;
            if (gelu) {
                c0 = 0.5f*c0*(1.f + erff(c0*0.70710678118654752f));
                c1 = 0.5f*c1*(1.f + erff(c1*0.70710678118654752f));
                c2 = 0.5f*c2*(1.f + erff(c2*0.70710678118654752f));
                c3 = 0.5f*c3*(1.f + erff(c3*0.70710678118654752f));
            }
            *(float2*)(C + (size_t)row0*N + col)       = make_float2(c0, c1);
            *(float2*)(C + (size_t)(row0 + 8)*N + col) = make_float2(c2, c3);
        }
    }
}

/* ============ tensor-core flash attention v2 (tf32, low-reg) ============ */
__global__ __launch_bounds__(128)
void attention_tc2(const float* __restrict__ qkv, const int* __restrict__ mask,
                   float* __restrict__ o)
{
    __shared__ __align__(16) float Ks[2][32][68];
    __shared__ __align__(16) float Vt[2][64][36];
    __shared__ __align__(16) float Ps[4][16][36];
    __shared__ float mb[S_];

    const int qq = blockIdx.x, h = blockIdx.y, b = blockIdx.z;
    const int tid = threadIdx.x, lane = tid & 31, w = tid >> 5;
    const int g = lane >> 2, tg = lane & 3;
    const int a_m = lane & 15;
    const int a_k = (lane >> 4) << 2;
    const int b_n = (lane & 7) + ((lane >> 4) << 3);
    const int b_k = ((lane >> 3) & 1) << 2;

    const size_t baseq = (size_t)b * S_ * QKV_ + (size_t)h * DH_;
    const size_t basek = baseq + D_;
    const size_t basev = baseq + 2*D_;
    const size_t baseo = (size_t)b * S_ * D_ + (size_t)h * DH_;
    const int q0 = qq*64 + w*16;

    mb[tid]       = mask[b*S_ + tid]       ? 0.f : -10000.f;
    mb[tid + 128] = mask[b*S_ + tid + 128] ? 0.f : -10000.f;

    float qf[8][4];
    #pragma unroll
    for (int kt = 0; kt < 8; kt++) {
        const float* qp = qkv + baseq + (size_t)(q0 + g)*QKV_ + kt*8 + tg;
        qf[kt][0] = 0.125f * qp[0];
        qf[kt][1] = 0.125f * qp[(size_t)8*QKV_];
        qf[kt][2] = 0.125f * qp[4];
        qf[kt][3] = 0.125f * qp[(size_t)8*QKV_ + 4];
    }

    float O[8][4];
    #pragma unroll
    for (int nt = 0; nt < 8; nt++)
        #pragma unroll
        for (int i = 0; i < 4; i++) O[nt][i] = 0.f;
    float mrow[2] = {-1e30f, -1e30f};
    float lrow[2] = {0.f, 0.f};

    const int kr = tid >> 2, kc = (tid & 3) << 2;
    const int vr = tid >> 2, vcb = (tid & 3) << 4;

    auto att_load_k = [&](int buf, int kv0) {
        cpasync16(&Ks[buf][kr][kc     ], qkv + basek + (size_t)(kv0 + kr)*QKV_ + kc     );
        cpasync16(&Ks[buf][kr][kc + 16], qkv + basek + (size_t)(kv0 + kr)*QKV_ + kc + 16);
        cpasync16(&Ks[buf][kr][kc + 32], qkv + basek + (size_t)(kv0 + kr)*QKV_ + kc + 32);
        cpasync16(&Ks[buf][kr][kc + 48], qkv + basek + (size_t)(kv0 + kr)*QKV_ + kc + 48);
        cp_commit();
    };

    float vreg[16];
    auto att_ldg_v = [&](int kv0) {
        #pragma unroll
        for (int j = 0; j < 4; j++)
            *(float4*)&vreg[4*j] =
                *(const float4*)(qkv + basev + (size_t)(kv0 + vr)*QKV_ + vcb + 4*j);
    };

    auto att_sts_v = [&](int buf) {
        #pragma unroll
        for (int s = 0; s < 16; s++) {
            int jj = (s + ((tid & 3) << 2)) & 15;
            Vt[buf][vcb + jj][vr] = vreg[jj];
        }
    };

    att_load_k(0, 0);
    att_ldg_v(0);
    att_sts_v(0);

    for (int it = 0; it < S_/32; it++) {
        cp_wait0();
        __syncthreads();
        const int cur = it & 1;
        const int kv0 = it*32;
        if (it + 1 < S_/32) {
            att_load_k(cur ^ 1, kv0 + 32);
            att_ldg_v(kv0 + 32);
        }

        float sc[4][4];
        #pragma unroll
        for (int nt = 0; nt < 4; nt++)
            #pragma unroll
            for (int i = 0; i < 4; i++) sc[nt][i] = 0.f;
        #pragma unroll
        for (int kt = 0; kt < 8; kt++) {
            uint32_t bfr[2][4];
            #pragma unroll
            for (int np = 0; np < 2; np++) {
                uint32_t addr = (uint32_t)__cvta_generic_to_shared(
                    &Ks[cur][np*16 + b_n][kt*8 + b_k]);
                ldsm_x4(bfr[np], addr);
            }
            #pragma unroll
            for (int nt = 0; nt < 4; nt++)
                mma_tf32(sc[nt], (const uint32_t*)qf[kt],
                         &bfr[nt >> 1][(nt & 1) * 2]);
        }

        #pragma unroll
        for (int nt = 0; nt < 4; nt++) {
            float m0 = mb[kv0 + nt*8 + 2*tg], m1 = mb[kv0 + nt*8 + 2*tg + 1];
            sc[nt][0] += m0; sc[nt][1] += m1;
            sc[nt][2] += m0; sc[nt][3] += m1;
        }
        #pragma unroll
        for (int rh = 0; rh < 2; rh++) {
            float mx = -1e30f;
            #pragma unroll
            for (int nt = 0; nt < 4; nt++)
                mx = fmaxf(mx, fmaxf(sc[nt][2*rh], sc[nt][2*rh+1]));
            mx = fmaxf(mx, __shfl_xor_sync(0xffffffffu, mx, 1));
            mx = fmaxf(mx, __shfl_xor_sync(0xffffffffu, mx, 2));
            float nm = fmaxf(mrow[rh], mx);
            float scale = __expf(mrow[rh] - nm);
            mrow[rh] = nm;
            float rs = 0.f;
            #pragma unroll
            for (int nt = 0; nt < 4; nt++) {
                float e0 = __expf(sc[nt][2*rh]   - nm);
                float e1 = __expf(sc[nt][2*rh+1] - nm);
                sc[nt][2*rh] = e0; sc[nt][2*rh+1] = e1;
                rs += e0 + e1;
            }
            rs += __shfl_xor_sync(0xffffffffu, rs, 1);
            rs += __shfl_xor_sync(0xffffffffu, rs, 2);
            lrow[rh] = lrow[rh]*scale + rs;
            #pragma unroll
            for (int nt = 0; nt < 8; nt++) {
                O[nt][2*rh]   *= scale;
                O[nt][2*rh+1] *= scale;
            }
        }
        #pragma unroll
        for (int nt = 0; nt < 4; nt++) {
            *(float2*)&Ps[w][g    ][nt*8 + 2*tg] = make_float2(sc[nt][0], sc[nt][1]);
            *(float2*)&Ps[w][g + 8][nt*8 + 2*tg] = make_float2(sc[nt][2], sc[nt][3]);
        }
        __syncwarp();

        #pragma unroll
        for (int kt = 0; kt < 4; kt++) {
            uint32_t pf[4];
            {
                uint32_t addr = (uint32_t)__cvta_generic_to_shared(
                    &Ps[w][a_m][kt*8 + a_k]);
                ldsm_x4(pf, addr);
            }
            uint32_t bfr[4][4];
            #pragma unroll
            for (int np = 0; np < 4; np++) {
                uint32_t addr = (uint32_t)__cvta_generic_to_shared(
                    &Vt[cur][np*16 + b_n][kt*8 + b_k]);
                ldsm_x4(bfr[np], addr);
            }
            #pragma unroll
            for (int nt = 0; nt < 8; nt++)
                mma_tf32(O[nt], pf, &bfr[nt >> 1][(nt & 1) * 2]);
        }

        if (it + 1 < S_/32) att_sts_v(cur ^ 1);
    }

    float inv0 = 1.f / lrow[0];
    float inv1 = 1.f / lrow[1];
    #pragma unroll
    for (int nt = 0; nt < 8; nt++) {
        int col = nt*8 + 2*tg;
        *(float2*)(o + baseo + (size_t)(q0 + g)*D_ + col) =
            make_float2(O[nt][0]*inv0, O[nt][1]*inv0);
        *(float2*)(o + baseo + (size_t)(q0 + g + 8)*D_ + col) =
            make_float2(O[nt][2]*inv1, O[nt][3]*inv1);
    }
}

/* ---------------- sense head ---------------- */
__global__ void sense_proj_kernel(const float* __restrict__ sense_emb,
                                  const float* __restrict__ att_Wk, float* __restrict__ sk)
{
    int idx = blockIdx.x*256 + threadIdx.x;
    int j = idx >> 6, a = idx & 63;
    float s = 0.f;
    for (int d = 0; d < D_; d++)
        s += sense_emb[(size_t)j*D_ + d] * att_Wk[(size_t)d*64 + a];
    sk[idx] = s;
}

__global__ void pun_proj_kernel(const float* __restrict__ x, const int* __restrict__ loc,
                                const float* __restrict__ att_Wq, float* __restrict__ pq)
{
    int idx = blockIdx.x*256 + threadIdx.x;
    int b = idx >> 6, a = idx & 63;
    int row = b*S_ + loc[b];
    float s = 0.f;
    for (int d = 0; d < D_; d++)
        s += x[(size_t)row*D_ + d] * att_Wq[(size_t)d*64 + a];
    pq[idx] = s;
}

__global__ void top2_kernel(const float* __restrict__ pq, const float* __restrict__ sk,
                            float* __restrict__ out)
{
    int b = blockIdx.x, j = threadIdx.x;
    __shared__ float sc[64];
    float s = 0.f;
    #pragma unroll 8
    for (int a = 0; a < 64; a++) s += pq[b*64 + a] * sk[j*64 + a];
    sc[j] = s * 0.125f;
    __syncthreads();
    if (j == 0) {
        int i1 = 0; float v1 = sc[0];
        for (int i = 1; i < 64; i++) if (sc[i] > v1) { v1 = sc[i]; i1 = i; }
        int i2 = -1; float v2 = -1e30f;
        for (int i = 0; i < 64; i++) if (i != i1 && sc[i] > v2) { v2 = sc[i]; i2 = i; }
        out[b*2 + 0] = (float)i1;
        out[b*2 + 1] = (float)i2;
    }
}

/* ---------------- launch ---------------- */
extern "C" void kernel_launch(void* const* d_in, const int* in_sizes, int n_in,
                              void* d_out, int out_size)
{
    (void)in_sizes; (void)n_in; (void)out_size;
    const int*   input_ids = (const int*)  d_in[0];
    const int*   token_tt  = (const int*)  d_in[1];
    const int*   attn_mask = (const int*)  d_in[2];
    const int*   location  = (const int*)  d_in[3];
    const float* sense_emb = (const float*)d_in[4];
    const float* word_emb  = (const float*)d_in[5];
    const float* pos_emb   = (const float*)d_in[6];
    const float* type_emb  = (const float*)d_in[7];
    const float* emb_ln_g  = (const float*)d_in[8];
    const float* emb_ln_b  = (const float*)d_in[9];
    const float* Wq  = (const float*)d_in[10]; const float* bq  = (const float*)d_in[11];
    const float* Wk  = (const float*)d_in[12]; const float* bk  = (const float*)d_in[13];
    const float* Wv  = (const float*)d_in[14]; const float* bv  = (const float*)d_in[15];
    const float* Wo  = (const float*)d_in[16]; const float* bo  = (const float*)d_in[17];
    const float* ln1g= (const float*)d_in[18]; const float* ln1b= (const float*)d_in[19];
    const float* W1  = (const float*)d_in[20]; const float* b1  = (const float*)d_in[21];
    const float* W2  = (const float*)d_in[22]; const float* b2  = (const float*)d_in[23];
    const float* ln2g= (const float*)d_in[24]; const float* ln2b= (const float*)d_in[25];
    const float* attWq=(const float*)d_in[26]; const float* attWk=(const float*)d_in[27];
    float* out = (float*)d_out;

    float *x,*qkv,*a,*t,*h,*sk,*pq;
    float *wqkvT,*bqkv,*woT,*w1T,*w2T;
    cudaGetSymbolAddress((void**)&x,    g_x);
    cudaGetSymbolAddress((void**)&qkv,  g_qkv);
    cudaGetSymbolAddress((void**)&a,    g_a);
    cudaGetSymbolAddress((void**)&t,    g_t);
    cudaGetSymbolAddress((void**)&h,    g_h);
    cudaGetSymbolAddress((void**)&sk,   g_sk);
    cudaGetSymbolAddress((void**)&pq,   g_pq);
    cudaGetSymbolAddress((void**)&wqkvT,g_wqkvT);
    cudaGetSymbolAddress((void**)&bqkv, g_bqkv);
    cudaGetSymbolAddress((void**)&woT,  g_woT);
    cudaGetSymbolAddress((void**)&w1T,  g_w1T);
    cudaGetSymbolAddress((void**)&w2T,  g_w2T);

    /* transpose weights into n-major layouts; QKV fused into one [2304][768] */
    {
        dim3 thr(32, 8);
        dim3 gDD(D_/32,  D_/32,  L_);
        dim3 g1 (FF_/32, D_/32,  L_);
        dim3 g2 (D_/32,  FF_/32, L_);
        size_t sDD = (size_t)D_*D_, sQKV = (size_t)QKV_*D_, sDF = (size_t)D_*FF_;
        transpose_f32<<<gDD, thr>>>(Wq, wqkvT, D_, D_, sDD, sQKV, 0);
        transpose_f32<<<gDD, thr>>>(Wk, wqkvT, D_, D_, sDD, sQKV, D_);
        transpose_f32<<<gDD, thr>>>(Wv, wqkvT, D_, D_, sDD, sQKV, 2*D_);
        transpose_f32<<<gDD, thr>>>(Wo, woT, D_, D_, sDD, sDD, 0);
        transpose_f32<<<g1,  thr>>>(W1, w1T, D_, FF_, sDF, sDF, 0);
        transpose_f32<<<g2,  thr>>>(W2, w2T, FF_, D_, sDF, sDF, 0);
        concat_bias_kernel<<<(L_*QKV_ + 255)/256, 256>>>(bq, bk, bv, bqkv);
    }

    embed_ln_kernel<<<NT_, 192>>>(input_ids, token_tt, word_emb, pos_emb, type_emb,
                                  emb_ln_g, emb_ln_b, x);

    dim3 gQ(QKV_/128, NT_/128);  /* N=2304 */
    dim3 gD(D_/128,   NT_/128);  /* N=768  */
    dim3 gF(FF_/128,  NT_/128);  /* N=3072 */

    for (int l = 0; l < L_; l++) {
        size_t wDD = (size_t)l*D_*D_;
        size_t wDF = (size_t)l*D_*FF_;
        gemm_tf32_ldsm<<<gQ, 256>>>(x, wqkvT + (size_t)l*QKV_*D_, bqkv + l*QKV_,
                                    qkv, NT_, QKV_, D_, 0);
        attention_tc2<<<dim3(4, H_, B_), 128>>>(qkv, attn_mask, a);
        gemm_tf32_ldsm<<<gD, 256>>>(a, woT + wDD, bo + l*D_, t, NT_, D_, D_, 0);
        add_ln_kernel<<<NT_, 192>>>(x, t, ln1g + l*D_, ln1b + l*D_);
        gemm_tf32_ldsm<<<gF, 256>>>(x, w1T + wDF, b1 + l*FF_, h, NT_, FF_, D_, 1);
        gemm_tf32_ldsm<<<gD, 256>>>(h, w2T + wDF, b2 + l*D_, t, NT_, D_, FF_, 0);
        add_ln_kernel<<<NT_, 192>>>(x, t, ln2g + l*D_, ln2b + l*D_);
    }

    sense_proj_kernel<<<16, 256>>>(sense_emb, attWk, sk);
    pun_proj_kernel<<<8, 256>>>(x, location, attWq, pq);
    top2_kernel<<<B_, 64>>>(pq, sk, out);
}